// round 15
// baseline (speedup 1.0000x reference)
#include <cuda_runtime.h>
#include <cuda_fp16.h>
#include <cstdint>

// ----------------------------------------------------------------------------
// GNNLayer: out = relu(x @ W^T + b); out[col[e],0] += x[e,0]
// Fused fp16 mma.sync GEMM: cp.async fp32 x -> A32 staging -> cooperative
// convert to fp16 A16 stage -> ldmatrix fragments (short MMA feed chain).
// Prep kernel: W fp16 + scatter sums S; S applied in epilogue (read+zero).
// ----------------------------------------------------------------------------

#define IN_DIM  512
#define OUT_DIM 512
#define MAXROWS 100096
#define BM      128
#define BN      128
#define BK      64
#define NCHUNK  (IN_DIM / BK)   // 8
#define THREADS 128

// A32 staging: 128 rows x 64 f32, row stride 272B (68w == 4 mod 32 -> LDS.128
// conflict-free). A16/B: 144B rows (ldmatrix conflict-free).
#define A32_ROWB 272
#define A16_ROWB 144
#define B_ROWB   144
#define SM_A32   0
#define A32_SIZE (BM * A32_ROWB)                 // 34816
#define SM_A16   A32_SIZE                         // + st*18432
#define A16_SIZE (BM * A16_ROWB)                 // 18432
#define SM_B     (A32_SIZE + 2 * A16_SIZE)       // 71680, + st*18432
#define B_SIZE   (BM * B_ROWB)                   // 18432
#define SM_TOTAL (SM_B + 2 * B_SIZE)             // 108544 (x2 CTA = 217088)

__device__ __half g_Wh[OUT_DIM * IN_DIM];
__device__ float  g_S[MAXROWS];                  // per-row scatter sums (col 0)

__device__ __forceinline__ uint32_t smem_u32(const void* p) {
    uint32_t a;
    asm("{ .reg .u64 t; cvta.to.shared.u64 t, %1; cvt.u32.u64 %0, t; }" : "=r"(a) : "l"(p));
    return a;
}
__device__ __forceinline__ void ldx4(uint32_t r[4], uint32_t addr) {
    asm volatile("ldmatrix.sync.aligned.m8n8.x4.shared.b16 {%0,%1,%2,%3}, [%4];"
                 : "=r"(r[0]), "=r"(r[1]), "=r"(r[2]), "=r"(r[3]) : "r"(addr));
}
__device__ __forceinline__ void ldx2(uint32_t r[2], uint32_t addr) {
    asm volatile("ldmatrix.sync.aligned.m8n8.x2.shared.b16 {%0,%1}, [%2];"
                 : "=r"(r[0]), "=r"(r[1]) : "r"(addr));
}
__device__ __forceinline__ void mma16816(float c[4], const uint32_t a[4], const uint32_t b[2]) {
    asm volatile("mma.sync.aligned.m16n8k16.row.col.f32.f16.f16.f32 "
                 "{%0,%1,%2,%3}, {%4,%5,%6,%7}, {%8,%9}, {%0,%1,%2,%3};"
                 : "+f"(c[0]), "+f"(c[1]), "+f"(c[2]), "+f"(c[3])
                 : "r"(a[0]), "r"(a[1]), "r"(a[2]), "r"(a[3]), "r"(b[0]), "r"(b[1]));
}
__device__ __forceinline__ void cp16(uint32_t dst, const void* src) {
    asm volatile("cp.async.cg.shared.global [%0], [%1], 16;"
                 :: "r"(dst), "l"(__cvta_generic_to_global(src)));
}
__device__ __forceinline__ float4 lds128f(uint32_t addr) {
    float4 v;
    asm volatile("ld.shared.v4.f32 {%0,%1,%2,%3}, [%4];"
                 : "=f"(v.x), "=f"(v.y), "=f"(v.z), "=f"(v.w) : "r"(addr));
    return v;
}
__device__ __forceinline__ void sts128(uint32_t addr, uint32_t a, uint32_t b,
                                       uint32_t c, uint32_t d) {
    asm volatile("st.shared.v4.b32 [%0], {%1,%2,%3,%4};"
                 :: "r"(addr), "r"(a), "r"(b), "r"(c), "r"(d) : "memory");
}
__device__ __forceinline__ uint32_t packh2(float a, float b) {
    __half2 h = __floats2half2_rn(a, b);
    return *reinterpret_cast<uint32_t*>(&h);
}

// ---------------- prep: W fp32->fp16 AND scatter-sum S ------------------------
#define WN4 (OUT_DIM * IN_DIM / 4)               // 65536
__global__ __launch_bounds__(256)
void prep_kernel(const float* __restrict__ W,
                 const float* __restrict__ x,
                 const int* __restrict__ edge_index, int E) {
    int i = blockIdx.x * blockDim.x + threadIdx.x;
    if (i < WN4) {
        float4 v = reinterpret_cast<const float4*>(W)[i];
        uint2 o;
        o.x = packh2(v.x, v.y);
        o.y = packh2(v.z, v.w);
        reinterpret_cast<uint2*>(g_Wh)[i] = o;
    }
    if (i < E) {
        int c = edge_index[E + i];                // row 1 of [2,E] int32
        atomicAdd(&g_S[c], x[(size_t)i * IN_DIM]);
    }
}

// ---------------- main GEMM kernel --------------------------------------------
__global__ __launch_bounds__(THREADS, 2)
void gemm_mma_kernel(const float* __restrict__ A,      // fp32 x
                     const float* __restrict__ bias,
                     float* __restrict__ C, int M) {
    extern __shared__ char smem[];
    const uint32_t sb = smem_u32(smem);
    const int tid    = threadIdx.x;
    const int lane   = tid & 31;
    const int wid    = tid >> 5;          // 0..3
    const int warp_m = wid >> 1;          // 0..1 (64 rows)
    const int warp_n = wid & 1;           // 0..1 (64 cols)
    const int row0   = blockIdx.y * BM;
    const int n0     = blockIdx.x * BN;

    // ldmatrix lane addressing (R7-proven)
    const uint32_t arow  = (uint32_t)(warp_m * 64 + (lane & 15));
    const uint32_t acolq = (uint32_t)((lane >> 4) << 3) * 2;       // 0 or 16B
    const uint32_t brow8 = (uint32_t)(lane & 7);
    const uint32_t bcolq = (uint32_t)(((lane >> 3) & 1) * 8) * 2;  // 0 or 16B

    float acc[4][8][4];
    #pragma unroll
    for (int mi = 0; mi < 4; mi++)
        #pragma unroll
        for (int ni = 0; ni < 8; ni++)
            #pragma unroll
            for (int j = 0; j < 4; j++) acc[mi][ni][j] = 0.f;

    // cp.async: A fp32 chunk into A32 staging (guarded); B fp16 into stage st
    auto issueA32 = [&](int kt) {
        const int k0 = kt * BK;
        #pragma unroll
        for (int i = 0; i < 16; i++) {
            int idx = i * THREADS + tid;
            int r = idx >> 4, u = idx & 15;
            int gr = row0 + r;
            if (gr < M)
                cp16(sb + SM_A32 + r * A32_ROWB + u * 16,
                     A + (size_t)gr * IN_DIM + k0 + u * 4);
        }
    };
    auto issueB = [&](int kt, int st) {
        const int k0 = kt * BK;
        #pragma unroll
        for (int i = 0; i < 8; i++) {
            int idx = i * THREADS + tid;
            int r = idx >> 3, u = idx & 7;
            cp16(sb + SM_B + st * B_SIZE + r * B_ROWB + u * 16,
                 g_Wh + (size_t)(n0 + r) * IN_DIM + k0 + u * 8);
        }
    };

    // cooperative convert: A32 staging -> fp16 A16 stage st (thread t = row t)
    auto convertA = [&](int st) {
        const uint32_t src = sb + SM_A32 + tid * A32_ROWB;
        const uint32_t dst = sb + SM_A16 + st * A16_SIZE + tid * A16_ROWB;
        #pragma unroll
        for (int i = 0; i < 8; i++) {
            float4 v0 = lds128f(src + (2 * i) * 16);
            float4 v1 = lds128f(src + (2 * i + 1) * 16);
            sts128(dst + i * 16,
                   packh2(v0.x, v0.y), packh2(v0.z, v0.w),
                   packh2(v1.x, v1.y), packh2(v1.z, v1.w));
        }
    };

    // ---- prologue -----------------------------------------------------------
    issueA32(0);
    issueB(0, 0);
    asm volatile("cp.async.commit_group;" ::: "memory");

    // ---- main loop ----------------------------------------------------------
    for (int kt = 0; kt < NCHUNK; kt++) {
        const int st = kt & 1;
        asm volatile("cp.async.wait_group 0;" ::: "memory");   // chunk kt landed
        __syncthreads();

        convertA(st);                                          // A32 -> A16(st)
        __syncthreads();                                       // A16 ready; A32 free

        if (kt + 1 < NCHUNK) { issueA32(kt + 1); issueB(kt + 1, st ^ 1); }
        asm volatile("cp.async.commit_group;" ::: "memory");   // (possibly empty)

        const uint32_t sbA = sb + SM_A16 + st * A16_SIZE;
        const uint32_t sbB = sb + SM_B   + st * B_SIZE;
        #pragma unroll
        for (int s = 0; s < 4; s++) {
            const uint32_t kb = (uint32_t)(s * 16) * 2;        // 32B per k16

            uint32_t af[4][4];
            #pragma unroll
            for (int mi = 0; mi < 4; mi++)
                ldx4(af[mi], sbA + (arow + mi * 16) * A16_ROWB + kb + acolq);

            uint32_t bf[8][2];
            #pragma unroll
            for (int ni = 0; ni < 8; ni++)
                ldx2(bf[ni], sbB + (warp_n * 64 + ni * 8 + brow8) * B_ROWB + kb + bcolq);

            #pragma unroll
            for (int mi = 0; mi < 4; mi++)
                #pragma unroll
                for (int ni = 0; ni < 8; ni++)
                    mma16816(acc[mi][ni], af[mi], bf[ni]);
        }
    }

    // ---- epilogue: bias + relu (+ scatter S on column 0) + float2 stores ----
    const bool col0_owner = (blockIdx.x == 0) && (warp_n == 0) && ((lane & 3) == 0);
    #pragma unroll
    for (int mi = 0; mi < 4; mi++) {
        int r = row0 + warp_m * 64 + mi * 16 + (lane >> 2);
        #pragma unroll
        for (int ni = 0; ni < 8; ni++) {
            int col = n0 + warp_n * 64 + ni * 8 + (lane & 3) * 2;
            float2 bv = *reinterpret_cast<const float2*>(bias + col);
            if (r < M) {
                float2 o;
                o.x = fmaxf(acc[mi][ni][0] + bv.x, 0.f);
                o.y = fmaxf(acc[mi][ni][1] + bv.y, 0.f);
                if (ni == 0 && col0_owner) {      // col == 0
                    o.x += g_S[r];
                    g_S[r] = 0.f;                 // restore for next replay
                }
                *reinterpret_cast<float2*>(C + (size_t)r * OUT_DIM + col) = o;
            }
            if (r + 8 < M) {
                float2 o;
                o.x = fmaxf(acc[mi][ni][2] + bv.x, 0.f);
                o.y = fmaxf(acc[mi][ni][3] + bv.y, 0.f);
                if (ni == 0 && col0_owner) {      // col == 0, row r+8
                    o.x += g_S[r + 8];
                    g_S[r + 8] = 0.f;
                }
                *reinterpret_cast<float2*>(C + (size_t)(r + 8) * OUT_DIM + col) = o;
            }
        }
    }
}

// ---------------- launch ------------------------------------------------------
extern "C" void kernel_launch(void* const* d_in, const int* in_sizes, int n_in,
                              void* d_out, int out_size) {
    const float* x   = (const float*)d_in[0];
    const int*   ei  = (const int*)d_in[1];
    const float* W   = (const float*)d_in[2];
    const float* b   = (const float*)d_in[3];
    float*       out = (float*)d_out;

    const int M = in_sizes[0] / IN_DIM;
    const int E = in_sizes[1] / 2;

    cudaFuncSetAttribute(gemm_mma_kernel, cudaFuncAttributeMaxDynamicSharedMemorySize, SM_TOTAL);

    const int prep_n = (E > WN4) ? E : WN4;
    prep_kernel<<<(prep_n + 255) / 256, 256>>>(W, x, ei, E);

    dim3 grid(OUT_DIM / BN, (M + BM - 1) / BM);   // 4 x 782
    gemm_mma_kernel<<<grid, THREADS, SM_TOTAL>>>(x, b, out, M);
}